// round 2
// baseline (speedup 1.0000x reference)
#include <cuda_runtime.h>
#include <mma.h>

using namespace nvcuda;

#define DIN   1024
#define DOUT  1024
#define BB    2
#define SEQ   2048
#define NH    16
#define HDIM  64
#define MROWS (BB * SEQ)            // 4096
#define QKVLD (3 * DOUT)            // 3072

#define INV_SCALE 0.17677669529663687f   // 1 / 1024^0.25

__device__ float g_qkv[(size_t)MROWS * QKVLD];  // [4096][3072]
__device__ float g_ctx[(size_t)MROWS * DOUT];   // [4096][1024]

__device__ __forceinline__ float to_tf32(float x) { return wmma::__float_to_tf32(x); }

__device__ __forceinline__ void cpa16(float* dst, const float* src) {
    unsigned s = (unsigned)__cvta_generic_to_shared(dst);
    asm volatile("cp.async.cg.shared.global [%0], [%1], 16;\n" :: "r"(s), "l"(src));
}

// ---------------------------------------------------------------------------
// GEMM: C[m, z*DOUT + n] = sum_k A[m,k] * Wz[n,k] (+ bias[n])
// 128x128 tile, BK=32, 256 threads (8 warps of 32x64), cp.async double buffer.
// ---------------------------------------------------------------------------
#define GEMM_SMEM (4 * 5120 * 4)   // 81920 bytes

__global__ void __launch_bounds__(256, 2)
gemm2_kernel(const float* __restrict__ A,
             const float* __restrict__ W0, const float* __restrict__ W1,
             const float* __restrict__ W2,
             const float* __restrict__ bias, float* __restrict__ C,
             int K, int ldc)
{
    extern __shared__ float gsm[];
    const int z = blockIdx.z;
    const float* W = (z == 0) ? W0 : ((z == 1) ? W1 : W2);
    const int coff = z * DOUT;
    const int m0 = blockIdx.y * 128;
    const int n0 = blockIdx.x * 128;
    const int tid  = threadIdx.x;
    const int warp = tid >> 5;
    const int wm = (warp >> 1) * 32;
    const int wn = (warp & 1) * 64;

    float* AsBuf[2] = { gsm,         gsm + 10240 };
    float* BsBuf[2] = { gsm + 5120,  gsm + 15360 };

    wmma::fragment<wmma::accumulator, 16, 16, 8, float> acc[2][4];
#pragma unroll
    for (int i = 0; i < 2; i++)
#pragma unroll
        for (int j = 0; j < 4; j++)
            wmma::fill_fragment(acc[i][j], 0.0f);

    const int NS = K / 32;

    // stage-0 prefetch
    {
        const float* Ab = A + (size_t)m0 * K;
        const float* Wb = W + (size_t)n0 * K;
#pragma unroll
        for (int i = tid; i < 1024; i += 256) {
            int r = i >> 3, c = (i & 7) * 4;
            cpa16(&AsBuf[0][r * 40 + c], &Ab[(size_t)r * K + c]);
            cpa16(&BsBuf[0][r * 40 + c], &Wb[(size_t)r * K + c]);
        }
        asm volatile("cp.async.commit_group;\n");
    }

    for (int ks = 0; ks < NS; ks++) {
        if (ks + 1 < NS) {
            int b = (ks + 1) & 1, gk = (ks + 1) * 32;
            const float* Ab = A + (size_t)m0 * K + gk;
            const float* Wb = W + (size_t)n0 * K + gk;
#pragma unroll
            for (int i = tid; i < 1024; i += 256) {
                int r = i >> 3, c = (i & 7) * 4;
                cpa16(&AsBuf[b][r * 40 + c], &Ab[(size_t)r * K + c]);
                cpa16(&BsBuf[b][r * 40 + c], &Wb[(size_t)r * K + c]);
            }
            asm volatile("cp.async.commit_group;\n");
            asm volatile("cp.async.wait_group 1;\n");
        } else {
            asm volatile("cp.async.wait_group 0;\n");
        }
        __syncthreads();

        const float* as = AsBuf[ks & 1];
        const float* bs = BsBuf[ks & 1];
#pragma unroll
        for (int kk = 0; kk < 32; kk += 8) {
            wmma::fragment<wmma::matrix_a, 16, 16, 8, wmma::precision::tf32, wmma::row_major> af[2];
            wmma::fragment<wmma::matrix_b, 16, 16, 8, wmma::precision::tf32, wmma::col_major> bf[4];
#pragma unroll
            for (int i = 0; i < 2; i++) {
                wmma::load_matrix_sync(af[i], as + (wm + 16 * i) * 40 + kk, 40);
#pragma unroll
                for (int e = 0; e < af[i].num_elements; e++) af[i].x[e] = to_tf32(af[i].x[e]);
            }
#pragma unroll
            for (int j = 0; j < 4; j++) {
                wmma::load_matrix_sync(bf[j], bs + (wn + 16 * j) * 40 + kk, 40);
#pragma unroll
                for (int e = 0; e < bf[j].num_elements; e++) bf[j].x[e] = to_tf32(bf[j].x[e]);
            }
#pragma unroll
            for (int i = 0; i < 2; i++)
#pragma unroll
                for (int j = 0; j < 4; j++)
                    wmma::mma_sync(acc[i][j], af[i], bf[j], acc[i][j]);
        }
        __syncthreads();
    }

    // Epilogue via smem staging (Cs[128][132] fits in gsm)
    float* Cs = gsm;
#pragma unroll
    for (int i = 0; i < 2; i++)
#pragma unroll
        for (int j = 0; j < 4; j++)
            wmma::store_matrix_sync(Cs + (wm + 16 * i) * 132 + wn + 16 * j,
                                    acc[i][j], 132, wmma::mem_row_major);
    __syncthreads();
#pragma unroll
    for (int i = tid; i < 4096; i += 256) {
        int r = i >> 5, c = (i & 31) * 4;
        float4 v = *(float4*)&Cs[r * 132 + c];
        if (bias) {
            v.x += bias[n0 + c];
            v.y += bias[n0 + c + 1];
            v.z += bias[n0 + c + 2];
            v.w += bias[n0 + c + 3];
        }
        *(float4*)&C[(size_t)(m0 + r) * ldc + coff + n0 + c] = v;
    }
}

// ---------------------------------------------------------------------------
// Flash attention (causal): 128-query tiles, 64-key tiles, 256 threads.
// Q staged once (tf32-rounded); K tile and S share a union buffer.
// ---------------------------------------------------------------------------
#define ILD 68
#define ATTN_SMEM (24192 * 4)   // 96768 bytes

__global__ void __launch_bounds__(256, 2)
attn2_kernel(const float* __restrict__ qkv, float* __restrict__ ctx)
{
    extern __shared__ float sm[];
    float* Qs   = sm;                // [128][68]
    float* SU   = sm + 8704;         // [128][68]  K tile (rows 0-63) / S
    float* Vs   = sm + 17408;        // [64][68]
    float* AF   = sm + 21760;        // [128][16]
    float* rowm = sm + 23808;        // [128]
    float* rowl = sm + 23936;        // [128]
    float* rowa = sm + 24064;        // [128]

    const int qt = (int)gridDim.x - 1 - (int)blockIdx.x;   // heavy tiles first
    const int bh = blockIdx.y;
    const int b  = bh >> 4;
    const int h  = bh & 15;
    const int q0 = qt * 128;
    const int tid  = threadIdx.x;
    const int warp = tid >> 5;

    const float* qbase = qkv + (size_t)b * SEQ * QKVLD + h * HDIM;
    const float* kbase = qbase + DOUT;
    const float* vbase = qbase + 2 * DOUT;

    // Stage Q tile, tf32-rounded
#pragma unroll
    for (int i = tid; i < 2048; i += 256) {
        int r = i >> 4, c = (i & 15) * 4;
        float4 v = *(const float4*)&qbase[(size_t)(q0 + r) * QKVLD + c];
        v.x = to_tf32(v.x); v.y = to_tf32(v.y); v.z = to_tf32(v.z); v.w = to_tf32(v.w);
        *(float4*)&Qs[r * ILD + c] = v;
    }
    if (tid < 128) { rowm[tid] = -1e30f; rowl[tid] = 0.0f; }

    wmma::fragment<wmma::accumulator, 16, 16, 8, float> of[4];
#pragma unroll
    for (int j = 0; j < 4; j++) wmma::fill_fragment(of[j], 0.0f);
    __syncthreads();

    const int nkv = q0 + 128;
    for (int j0 = 0; j0 < nkv; j0 += 64) {
        // Stage K (into SU rows 0..63) and V, tf32-rounded
#pragma unroll
        for (int i = tid; i < 1024; i += 256) {
            int r = i >> 4, c = (i & 15) * 4;
            float4 kv = *(const float4*)&kbase[(size_t)(j0 + r) * QKVLD + c];
            kv.x = to_tf32(kv.x); kv.y = to_tf32(kv.y); kv.z = to_tf32(kv.z); kv.w = to_tf32(kv.w);
            *(float4*)&SU[r * ILD + c] = kv;
            float4 vv = *(const float4*)&vbase[(size_t)(j0 + r) * QKVLD + c];
            vv.x = to_tf32(vv.x); vv.y = to_tf32(vv.y); vv.z = to_tf32(vv.z); vv.w = to_tf32(vv.w);
            *(float4*)&Vs[r * ILD + c] = vv;
        }
        __syncthreads();

        const bool active = (j0 <= q0 + warp * 16 + 15);  // warp has >=1 unmasked row
        wmma::fragment<wmma::accumulator, 16, 16, 8, float> sf[4];
        if (active) {
#pragma unroll
            for (int j = 0; j < 4; j++) wmma::fill_fragment(sf[j], 0.0f);
#pragma unroll
            for (int s = 0; s < 8; s++) {
                wmma::fragment<wmma::matrix_a, 16, 16, 8, wmma::precision::tf32, wmma::row_major> qa;
                wmma::load_matrix_sync(qa, Qs + (warp * 16) * ILD + s * 8, ILD);
#pragma unroll
                for (int j = 0; j < 4; j++) {
                    wmma::fragment<wmma::matrix_b, 16, 16, 8, wmma::precision::tf32, wmma::col_major> kb;
                    wmma::load_matrix_sync(kb, SU + (j * 16) * ILD + s * 8, ILD);
                    wmma::mma_sync(sf[j], qa, kb, sf[j]);
                }
            }
        }
        __syncthreads();   // all K reads complete before S overwrites SU
        if (active) {
#pragma unroll
            for (int j = 0; j < 4; j++)
                wmma::store_matrix_sync(SU + (warp * 16) * ILD + j * 16, sf[j], ILD,
                                        wmma::mem_row_major);
        }
        __syncthreads();

        // Online softmax: thread pair (t, t^1) owns row r, 32 cols each
        {
            const int r  = tid >> 1;
            const int c0 = (tid & 1) * 32;
            const int qg = q0 + r;
            const int lim = qg - j0 - c0;        // valid cols: c <= lim
            float* Srow = SU + r * ILD + c0;
            float mx = -1e30f;
#pragma unroll
            for (int c = 0; c < 32; c++) {
                float s = (c <= lim) ? Srow[c] * INV_SCALE : -1e30f;
                mx = fmaxf(mx, s);
            }
            mx = fmaxf(mx, __shfl_xor_sync(0xffffffffu, mx, 1));
            const float mo = rowm[r];
            const float mn = fmaxf(mo, mx);
            float ls = 0.0f;
#pragma unroll
            for (int c = 0; c < 32; c++) {
                float p = (c <= lim) ? __expf(Srow[c] * INV_SCALE - mn) : 0.0f;
                Srow[c] = to_tf32(p);
                ls += p;
            }
            ls += __shfl_xor_sync(0xffffffffu, ls, 1);
            if ((tid & 1) == 0) {
                float a = __expf(mo - mn);
                rowm[r] = mn;
                rowl[r] = rowl[r] * a + ls;
                rowa[r] = a;
            }
        }
        __syncthreads();

        // Broadcast alpha into AF[128][16]
#pragma unroll
        for (int i = tid; i < 2048; i += 256) AF[i] = rowa[i >> 4];
        __syncthreads();

        // Rescale O (layout-agnostic identical-frag trick)
        {
            wmma::fragment<wmma::accumulator, 16, 16, 8, float> af;
            wmma::load_matrix_sync(af, AF + (warp * 16) * 16, 16, wmma::mem_row_major);
#pragma unroll
            for (int j = 0; j < 4; j++)
#pragma unroll
                for (int e = 0; e < af.num_elements; e++) of[j].x[e] *= af.x[e];
        }

        // O += P V
        if (active) {
#pragma unroll
            for (int s = 0; s < 8; s++) {
                wmma::fragment<wmma::matrix_a, 16, 16, 8, wmma::precision::tf32, wmma::row_major> pf;
                wmma::load_matrix_sync(pf, SU + (warp * 16) * ILD + s * 8, ILD);
#pragma unroll
                for (int j = 0; j < 4; j++) {
                    wmma::fragment<wmma::matrix_b, 16, 16, 8, wmma::precision::tf32, wmma::row_major> vf;
                    wmma::load_matrix_sync(vf, Vs + (s * 8) * ILD + j * 16, ILD);
                    wmma::mma_sync(of[j], pf, vf, of[j]);
                }
            }
        }
        __syncthreads();
    }

    // Epilogue
#pragma unroll
    for (int j = 0; j < 4; j++)
        wmma::store_matrix_sync(SU + (warp * 16) * ILD + j * 16, of[j], ILD,
                                wmma::mem_row_major);
    __syncthreads();
#pragma unroll
    for (int i = tid; i < 2048; i += 256) {
        int r = i >> 4, c = (i & 15) * 4;
        float inv = 1.0f / rowl[r];
        float4 v = *(float4*)&SU[r * ILD + c];
        v.x *= inv; v.y *= inv; v.z *= inv; v.w *= inv;
        *(float4*)&ctx[((size_t)b * SEQ + q0 + r) * DOUT + h * HDIM + c] = v;
    }
}

// ---------------------------------------------------------------------------
extern "C" void kernel_launch(void* const* d_in, const int* in_sizes, int n_in,
                              void* d_out, int out_size)
{
    (void)in_sizes; (void)n_in; (void)out_size;
    const float* x  = (const float*)d_in[0];
    const float* Wq = (const float*)d_in[1];
    const float* Wk = (const float*)d_in[2];
    const float* Wv = (const float*)d_in[3];
    const float* Wo = (const float*)d_in[4];
    const float* bo = (const float*)d_in[5];
    float* out = (float*)d_out;

    float *qkv = nullptr, *ctx = nullptr;
    cudaGetSymbolAddress((void**)&qkv, g_qkv);
    cudaGetSymbolAddress((void**)&ctx, g_ctx);

    cudaFuncSetAttribute(gemm2_kernel, cudaFuncAttributeMaxDynamicSharedMemorySize, GEMM_SMEM);
    cudaFuncSetAttribute(attn2_kernel, cudaFuncAttributeMaxDynamicSharedMemorySize, ATTN_SMEM);

    // Fused QKV projections (z selects Wq/Wk/Wv, writes q|k|v slabs)
    gemm2_kernel<<<dim3(DOUT / 128, MROWS / 128, 3), 256, GEMM_SMEM>>>(
        x, Wq, Wk, Wv, nullptr, qkv, DIN, QKVLD);

    // Causal flash attention
    attn2_kernel<<<dim3(SEQ / 128, BB * NH), 256, ATTN_SMEM>>>(qkv, ctx);

    // Output projection + bias
    gemm2_kernel<<<dim3(DOUT / 128, MROWS / 128, 1), 256, GEMM_SMEM>>>(
        ctx, Wo, nullptr, nullptr, bo, out, DOUT, DOUT);
}